// round 13
// baseline (speedup 1.0000x reference)
#include <cuda_runtime.h>

// Problem dims
#define NCC 4
#define BSZ 16
#define NTT 32
#define SSLICE (BSZ*64*64*12)   // 786432 floats per (BS,H,W,OC) slab

// Persistent device state
__device__ __align__(16) float g_slabs[5][SSLICE];
__device__ __align__(16) float g_class_c[NCC*SSLICE];
__device__ __align__(16) float g_genh[2][SSLICE];
__device__ __align__(16) float g_genc[SSLICE];

// Reordered weights: [k][ic][quarter][gate][3]; quarter qq owns oc channels
// gate*12 + qq*3 .. +2 of every gate. Per (ic,qq): 12 contiguous floats.
__device__ __align__(16) float g_wg[9*60*48];
__device__ __align__(16) float g_wc[9*36*48];

// Slab schedule: g_rslab[t*4+c] = slab holding class_h[c] at start of step t;
// g_wslab[t] = slab step t's cls writes h_new into.
__device__ int g_rslab[NTT*NCC];
__device__ int g_wslab[NTT];

__device__ __forceinline__ float hsig(float x) {
    return fminf(fmaxf(x + 3.0f, 0.0f), 6.0f) * (1.0f/6.0f);
}

typedef unsigned long long ull;

__device__ __forceinline__ ull pack2(float x) {
    ull r;
    unsigned int xi = __float_as_uint(x);
    asm("mov.b64 %0, {%1, %1};" : "=l"(r) : "r"(xi));
    return r;
}
__device__ __forceinline__ void ffma2(ull& d, ull a, ull b) {
    asm("fma.rn.f32x2 %0, %1, %2, %0;" : "+l"(d) : "l"(a), "l"(b));
}
__device__ __forceinline__ float2 unpack2(ull v) {
    float2 r;
    asm("mov.b64 {%0, %1}, %2;" : "=f"(r.x), "=f"(r.y) : "l"(v));
    return r;
}

// --------------------------------------------------------------------------
// 12-channel conv tap, 12-oc quarter per thread. Channel stride in the
// reordered layout = 48 floats = 12 ulonglong2; this thread's 12 floats
// are contiguous (3 u2, 48B-aligned).
// xb channel-major: channel icc at xb[icc*660], next row +66.
// --------------------------------------------------------------------------
__device__ __forceinline__ void conv12q(const float* __restrict__ sWk,
                                        const float* __restrict__ xb,
                                        ull* __restrict__ acc0,
                                        ull* __restrict__ acc1)
{
    const ulonglong2* wp = (const ulonglong2*)sWk;
    #pragma unroll 2
    for (int icc = 0; icc < 12; ++icc) {
        ull xp0 = pack2(xb[icc*660]);
        ull xp1 = pack2(xb[icc*660 + 66]);
        const ulonglong2* w = wp + icc*12;   // 48-float channel stride
        #pragma unroll
        for (int p = 0; p < 3; ++p) {
            ulonglong2 ww = w[p];
            ffma2(acc0[2*p],   xp0, ww.x);
            ffma2(acc0[2*p+1], xp0, ww.y);
            ffma2(acc1[2*p],   xp1, ww.x);
            ffma2(acc1[2*p+1], xp1, ww.y);
        }
    }
}

// --------------------------------------------------------------------------
__global__ void zero_kernel(float* __restrict__ out, const int* __restrict__ cids)
{
    const int tid    = blockIdx.x * blockDim.x + threadIdx.x;
    const int stride = gridDim.x * blockDim.x;
    for (int i = tid; i < 5*SSLICE; i += stride)
        (&g_slabs[0][0])[i] = 0.0f;
    for (int i = tid; i < NCC*SSLICE; i += stride)
        g_class_c[i] = 0.0f;
    for (int i = tid; i < SSLICE; i += stride) {
        g_genh[0][i] = 0.0f;
        g_genc[i]    = 0.0f;
        out[i]       = 0.0f;
    }
    if (tid == 0) {
        int slab[NCC] = {0, 1, 2, 3};
        int spare = 4;
        for (int t = 0; t < NTT; ++t) {
            int cid = cids[t];
            #pragma unroll
            for (int c = 0; c < NCC; ++c) g_rslab[t*4 + c] = slab[c];
            g_wslab[t] = spare;
            int old = slab[cid];
            slab[cid] = spare;
            spare = old;
        }
    }
}

// --------------------------------------------------------------------------
// One-time weight reorder into [k][ic][quarter][gate][3] layout (scalar).
// src oc = gate*12 + qq*3 + j.
// --------------------------------------------------------------------------
__global__ void reorder_kernel(const float* __restrict__ Wxg, const float* __restrict__ Whg,
                               const float* __restrict__ Wxc, const float* __restrict__ Whc)
{
    const int tid    = blockIdx.x * blockDim.x + threadIdx.x;
    const int stride = gridDim.x * blockDim.x;
    for (int e = tid; e < 9*60*48; e += stride) {
        int j    = e % 3;
        int gate = (e/3) & 3;
        int qq   = (e/12) & 3;
        int ic   = (e/48) % 60;
        int k    = e / 2880;
        int oc   = gate*12 + qq*3 + j;
        float v  = (ic < 48) ? Wxg[(k*48 + ic)*48 + oc]
                             : Whg[(k*12 + (ic - 48))*48 + oc];
        g_wg[((k*60 + ic)*4 + qq)*12 + gate*3 + j] = v;
    }
    for (int e = tid; e < 9*36*48; e += stride) {
        int j    = e % 3;
        int gate = (e/3) & 3;
        int qq   = (e/12) & 3;
        int ic   = (e/48) % 36;
        int k    = e / 1728;
        int oc   = gate*12 + qq*3 + j;
        float v  = (ic < 24) ? Wxc[(k*24 + ic)*48 + oc]
                             : Whc[(k*12 + (ic - 24))*48 + oc];
        g_wc[((k*36 + ic)*4 + qq)*12 + gate*3 + j] = v;
    }
}

// --------------------------------------------------------------------------
__device__ __forceinline__ float4 ldsrc_gen(const float* __restrict__ bankp,
                                            const float* __restrict__ genh_in,
                                            int ch, int pidx, int q, bool ok)
{
    if (!ok) return make_float4(0.f, 0.f, 0.f, 0.f);
    const float* src = (ch < 4)
        ? bankp   + (size_t)(pidx & 16383)*48 + ch*12
        : genh_in + (size_t)pidx*12;
    return *(const float4*)(src + q*4);
}

__device__ __forceinline__ float4 ldsrc_cls(const float* __restrict__ frame,
                                            const float* __restrict__ genh_new,
                                            const float* __restrict__ chh,
                                            int ch, int pidx, int q, bool ok)
{
    if (!ok) return make_float4(0.f, 0.f, 0.f, 0.f);
    const float* src = (ch == 0) ? frame + (size_t)(pidx & 4095)*12
                     : (ch == 1) ? genh_new + (size_t)pidx*12
                                 : chh + (size_t)pidx*12;
    return *(const float4*)(src + q*4);
}

// ==========================================================================
// General cell. grid (8,16)=(row-tile,batch), block 1024 = 64 cols x 4
// rowgroups x 4 oc-quarters; each thread 2 rows x 12 oc -> local epilogue.
// 32 warps = 8/SMSP for latency hiding; FMA pipe remains the binder.
// ==========================================================================
#define A_SW   (9*60*48)            // 25920 floats
#define A_SIN  (12*660)             // 7920 floats, [icc][10 rows x 66 cols]
#define A_SMEM_BYTES ((A_SW + A_SIN + 48)*4)

__global__ __launch_bounds__(1024, 1)
void gen_cell_kernel(const float* __restrict__ bias, int t, int par)
{
    extern __shared__ float smem[];
    float* sW  = smem;                 // [9][60][4][12]
    float* sIn = smem + A_SW;          // [12][660]
    float* sB  = smem + A_SW + A_SIN;  // [48] bias

    const int tid = threadIdx.x;
    const int tx  = tid & 63;
    const int rg  = (tid >> 6) & 3;
    const int qq  = tid >> 8;          // 0..3
    const int b   = blockIdx.y;
    const int y0  = blockIdx.x * 8;
    const float* bankp = g_slabs[g_rslab[t*4 + (b >> 2)]];

    const float* genh_in  = g_genh[par];
    float*       genh_out = g_genh[par ^ 1];

    // Stage reordered weights: pure linear float4 copy (6480 float4)
    {
        const float4* s4 = (const float4*)g_wg;
        float4*       d4 = (float4*)sW;
        #pragma unroll
        for (int i = 0; i < 7; ++i) {
            int e = tid + i*1024;
            if (e < 6480) d4[e] = s4[e];
        }
    }
    if (tid < 12) ((float4*)sB)[tid] = ((const float4*)bias)[tid];

    // Staging coordinates (2 slots/thread at 1024-stride; invariant)
    int pq[2], ppidx[2];
    int pbase[2];
    bool pok[2], pinr[2];
    #pragma unroll
    for (int i = 0; i < 2; ++i) {
        int e  = tid + i*1024;
        bool inr = e < 1980;
        int px = e/3, q = e - px*3;
        int yy = px/66, xx = px - yy*66;
        int gy = y0 + yy - 1, gx = xx - 1;
        bool inb = inr && (unsigned)gy < 64u && (unsigned)gx < 64u;
        pq[i] = q;
        pbase[i] = q*4*660 + px;
        ppidx[i] = inb ? ((b*64 + gy)*64 + gx) : 0;
        pok[i] = inb; pinr[i] = inr;
    }

    ull acc0[6], acc1[6];
    #pragma unroll
    for (int p = 0; p < 6; ++p) { acc0[p] = 0ull; acc1[p] = 0ull; }

    float4 pf[2];
    #pragma unroll
    for (int i = 0; i < 2; ++i)
        pf[i] = ldsrc_gen(bankp, genh_in, 0, ppidx[i], pq[i], pok[i]);

    #pragma unroll 1
    for (int ch = 0; ch < 5; ++ch) {
        __syncthreads();
        #pragma unroll
        for (int i = 0; i < 2; ++i) {
            if (pinr[i]) {
                sIn[pbase[i]]        = pf[i].x;
                sIn[pbase[i] +  660] = pf[i].y;
                sIn[pbase[i] + 1320] = pf[i].z;
                sIn[pbase[i] + 1980] = pf[i].w;
            }
        }
        __syncthreads();
        if (ch < 4) {
            #pragma unroll
            for (int i = 0; i < 2; ++i)
                pf[i] = ldsrc_gen(bankp, genh_in, ch + 1, ppidx[i], pq[i], pok[i]);
        }

        #pragma unroll 1
        for (int k = 0; k < 9; ++k) {
            const int ky = k / 3;
            const int kx = k - ky*3;
            conv12q(sW + ((k*60 + ch*12)*4 + qq)*12,
                    sIn + (rg*2 + ky)*66 + tx + kx,
                    acc0, acc1);
        }
    }

    // Local LSTM epilogue: channels qq*3..qq*3+2 of all gates
    #pragma unroll
    for (int r = 0; r < 2; ++r) {
        ull* accr = r ? acc1 : acc0;
        float z[12];   // [i0..2 | f0..2 | g0..2 | o0..2]
        #pragma unroll
        for (int p = 0; p < 6; ++p) {
            float2 v = unpack2(accr[p]);
            z[2*p] = v.x; z[2*p+1] = v.y;
        }
        const int gy  = y0 + rg*2 + r;
        const int idx = ((b*64 + gy)*64 + tx)*12 + qq*3;
        #pragma unroll
        for (int j = 0; j < 3; ++j) {
            float zi = z[j]     + sB[qq*3 + j];
            float zf = z[3 + j] + sB[12 + qq*3 + j];
            float zg = z[6 + j] + sB[24 + qq*3 + j];
            float zo = z[9 + j] + sB[36 + qq*3 + j];
            float fi = hsig(zi), ff = hsig(zf), fo = hsig(zo);
            float cn = ff * g_genc[idx + j] + fi * tanhf(zg);
            g_genc[idx + j]   = cn;
            genh_out[idx + j] = fo * tanhf(cn);
        }
    }
}

// ==========================================================================
// Class cell: 36 in-ch = 3 chunks of 12 (frame, fresh gen_h, class_h[cid]).
// Same 1024-thread layout. Writes h_new into slab wslab[t]; accumulates out.
// ==========================================================================
#define B_SW   (9*36*48)            // 15552 floats
#define B_SIN  (12*660)
#define B_SMEM_BYTES ((B_SW + B_SIN + 48)*4)

__global__ __launch_bounds__(1024, 1)
void cls_cell_kernel(const float* __restrict__ x, const int* __restrict__ class_ids,
                     const float* __restrict__ bias, int t, int par,
                     float* __restrict__ out)
{
    extern __shared__ float smem[];
    float* sW  = smem;                 // [9][36][4][12]
    float* sIn = smem + B_SW;
    float* sB  = smem + B_SW + B_SIN;

    const int tid = threadIdx.x;
    const int tx  = tid & 63;
    const int rg  = (tid >> 6) & 3;
    const int qq  = tid >> 8;
    const int b   = blockIdx.y;
    const int y0  = blockIdx.x * 8;
    const int cid = __ldg(class_ids + t);

    const float* genh_new = g_genh[par ^ 1];
    const float* chh      = g_slabs[g_rslab[t*4 + cid]];
    float*       hnew     = g_slabs[g_wslab[t]];
    const float* frame    = x + (size_t)(b*NTT + t)*4096*12;

    {
        const float4* s4 = (const float4*)g_wc;
        float4*       d4 = (float4*)sW;
        #pragma unroll
        for (int i = 0; i < 4; ++i) {
            int e = tid + i*1024;
            if (e < 3888) d4[e] = s4[e];
        }
    }
    if (tid < 12) ((float4*)sB)[tid] = ((const float4*)bias)[tid];

    int pq[2], ppidx[2], pbase[2];
    bool pok[2], pinr[2];
    #pragma unroll
    for (int i = 0; i < 2; ++i) {
        int e  = tid + i*1024;
        bool inr = e < 1980;
        int px = e/3, q = e - px*3;
        int yy = px/66, xx = px - yy*66;
        int gy = y0 + yy - 1, gx = xx - 1;
        bool inb = inr && (unsigned)gy < 64u && (unsigned)gx < 64u;
        pq[i] = q;
        pbase[i] = q*4*660 + px;
        ppidx[i] = inb ? ((b*64 + gy)*64 + gx) : 0;
        pok[i] = inb; pinr[i] = inr;
    }

    ull acc0[6], acc1[6];
    #pragma unroll
    for (int p = 0; p < 6; ++p) { acc0[p] = 0ull; acc1[p] = 0ull; }

    float4 pf[2];
    #pragma unroll
    for (int i = 0; i < 2; ++i)
        pf[i] = ldsrc_cls(frame, genh_new, chh, 0, ppidx[i], pq[i], pok[i]);

    #pragma unroll 1
    for (int ch = 0; ch < 3; ++ch) {
        __syncthreads();
        #pragma unroll
        for (int i = 0; i < 2; ++i) {
            if (pinr[i]) {
                sIn[pbase[i]]        = pf[i].x;
                sIn[pbase[i] +  660] = pf[i].y;
                sIn[pbase[i] + 1320] = pf[i].z;
                sIn[pbase[i] + 1980] = pf[i].w;
            }
        }
        __syncthreads();
        if (ch < 2) {
            #pragma unroll
            for (int i = 0; i < 2; ++i)
                pf[i] = ldsrc_cls(frame, genh_new, chh, ch + 1, ppidx[i], pq[i], pok[i]);
        }

        #pragma unroll 1
        for (int k = 0; k < 9; ++k) {
            const int ky = k / 3;
            const int kx = k - ky*3;
            conv12q(sW + ((k*36 + ch*12)*4 + qq)*12,
                    sIn + (rg*2 + ky)*66 + tx + kx,
                    acc0, acc1);
        }
    }

    float* chc = g_class_c + (size_t)cid * SSLICE;

    #pragma unroll
    for (int r = 0; r < 2; ++r) {
        ull* accr = r ? acc1 : acc0;
        float z[12];
        #pragma unroll
        for (int p = 0; p < 6; ++p) {
            float2 v = unpack2(accr[p]);
            z[2*p] = v.x; z[2*p+1] = v.y;
        }
        const int gy  = y0 + rg*2 + r;
        const int idx = ((b*64 + gy)*64 + tx)*12 + qq*3;
        #pragma unroll
        for (int j = 0; j < 3; ++j) {
            float zi = z[j]     + sB[qq*3 + j];
            float zf = z[3 + j] + sB[12 + qq*3 + j];
            float zg = z[6 + j] + sB[24 + qq*3 + j];
            float zo = z[9 + j] + sB[36 + qq*3 + j];
            float fi = hsig(zi), ff = hsig(zf), fo = hsig(zo);
            float cn = ff * chc[idx + j] + fi * tanhf(zg);
            float hn = fo * tanhf(cn);
            chc[idx + j]  = cn;
            hnew[idx + j] = hn;
            out[idx + j] += hn;
        }
    }
}

// --------------------------------------------------------------------------
extern "C" void kernel_launch(void* const* d_in, const int* in_sizes, int n_in,
                              void* d_out, int out_size)
{
    const float* x    = (const float*)d_in[0];
    const int*   cids = (const int*)d_in[1];
    const float* Wxg  = (const float*)d_in[2];
    const float* Whg  = (const float*)d_in[3];
    const float* bg   = (const float*)d_in[4];
    const float* Wxc  = (const float*)d_in[5];
    const float* Whc  = (const float*)d_in[6];
    const float* bc   = (const float*)d_in[7];
    float* out = (float*)d_out;

    cudaFuncSetAttribute(gen_cell_kernel, cudaFuncAttributeMaxDynamicSharedMemorySize, A_SMEM_BYTES);
    cudaFuncSetAttribute(cls_cell_kernel, cudaFuncAttributeMaxDynamicSharedMemorySize, B_SMEM_BYTES);

    zero_kernel<<<1024, 256>>>(out, cids);
    reorder_kernel<<<64, 256>>>(Wxg, Whg, Wxc, Whc);

    for (int t = 0; t < NTT; ++t) {
        const int par = t & 1;
        gen_cell_kernel<<<dim3(8, 16), 1024, A_SMEM_BYTES>>>(bg, t, par);
        cls_cell_kernel<<<dim3(8, 16), 1024, B_SMEM_BYTES>>>(x, cids, bc, t, par, out);
    }
}

// round 14
// speedup vs baseline: 2.4661x; 2.4661x over previous
#include <cuda_runtime.h>

// Problem dims
#define NCC 4
#define BSZ 16
#define NTT 32
#define SSLICE (BSZ*64*64*12)   // 786432 floats per (BS,H,W,OC) slab

// Persistent device state
__device__ __align__(16) float g_slabs[5][SSLICE];
__device__ __align__(16) float g_class_c[NCC*SSLICE];
__device__ __align__(16) float g_genh[2][SSLICE];
__device__ __align__(16) float g_genc[SSLICE];

// Cached class-conv pre-activations: Z[pixel][48] = conv(class_view, Wx_g),
// stored in the reordered [third][gate][4] channel order (matches acc layout).
__device__ __align__(16) float g_Z[4*SSLICE];

// Reordered weights: [k][ic][third][gate][4]; third th owns oc channels
// gate*12 + th*4 .. +3 of every gate.
__device__ __align__(16) float g_wg[9*60*48];
__device__ __align__(16) float g_wc[9*36*48];

// Slab schedule: g_rslab[t*4+c] = slab holding class_h[c] at start of step t;
// g_wslab[t] = slab step t's cls writes h_new into.
__device__ int g_rslab[NTT*NCC];
__device__ int g_wslab[NTT];

__device__ __forceinline__ float hsig(float x) {
    return fminf(fmaxf(x + 3.0f, 0.0f), 6.0f) * (1.0f/6.0f);
}

typedef unsigned long long ull;

__device__ __forceinline__ ull pack2(float x) {
    ull r;
    unsigned int xi = __float_as_uint(x);
    asm("mov.b64 %0, {%1, %1};" : "=l"(r) : "r"(xi));
    return r;
}
__device__ __forceinline__ ull packpair(float a, float b) {
    ull r;
    asm("mov.b64 %0, {%1, %2};" : "=l"(r) : "f"(a), "f"(b));
    return r;
}
__device__ __forceinline__ void ffma2(ull& d, ull a, ull b) {
    asm("fma.rn.f32x2 %0, %1, %2, %0;" : "+l"(d) : "l"(a), "l"(b));
}
__device__ __forceinline__ float2 unpack2(ull v) {
    float2 r;
    asm("mov.b64 {%0, %1}, %2;" : "=f"(r.x), "=f"(r.y) : "l"(v));
    return r;
}

// --------------------------------------------------------------------------
// 12-channel conv tap, 16-oc third per thread. Channel stride 48 floats =
// 12 ulonglong2; this thread's 16 floats contiguous (4 u2).
// xb channel-major: channel icc at xb[icc*660], next row +66.
// --------------------------------------------------------------------------
__device__ __forceinline__ void conv12t(const float* __restrict__ sWk,
                                        const float* __restrict__ xb,
                                        ull* __restrict__ acc0,
                                        ull* __restrict__ acc1)
{
    const ulonglong2* wp = (const ulonglong2*)sWk;
    #pragma unroll 2
    for (int icc = 0; icc < 12; ++icc) {
        ull xp0 = pack2(xb[icc*660]);
        ull xp1 = pack2(xb[icc*660 + 66]);
        const ulonglong2* w = wp + icc*12;   // 48-float channel stride
        #pragma unroll
        for (int p = 0; p < 4; ++p) {
            ulonglong2 ww = w[p];
            ffma2(acc0[2*p],   xp0, ww.x);
            ffma2(acc0[2*p+1], xp0, ww.y);
            ffma2(acc1[2*p],   xp1, ww.x);
            ffma2(acc1[2*p+1], xp1, ww.y);
        }
    }
}

// --------------------------------------------------------------------------
__global__ void zero_kernel(float* __restrict__ out, const int* __restrict__ cids)
{
    const int tid    = blockIdx.x * blockDim.x + threadIdx.x;
    const int stride = gridDim.x * blockDim.x;
    for (int i = tid; i < 5*SSLICE; i += stride)
        (&g_slabs[0][0])[i] = 0.0f;
    for (int i = tid; i < 4*SSLICE; i += stride) {
        g_class_c[i] = 0.0f;
        g_Z[i]       = 0.0f;
    }
    for (int i = tid; i < SSLICE; i += stride) {
        g_genh[0][i] = 0.0f;
        g_genc[i]    = 0.0f;
        out[i]       = 0.0f;
    }
    if (tid == 0) {
        int slab[NCC] = {0, 1, 2, 3};
        int spare = 4;
        for (int t = 0; t < NTT; ++t) {
            int cid = cids[t];
            #pragma unroll
            for (int c = 0; c < NCC; ++c) g_rslab[t*4 + c] = slab[c];
            g_wslab[t] = spare;
            int old = slab[cid];
            slab[cid] = spare;
            spare = old;
        }
    }
}

// --------------------------------------------------------------------------
// One-time weight reorder into [k][ic][third][gate][4] layout (R11-proven).
// --------------------------------------------------------------------------
__global__ void reorder_kernel(const float* __restrict__ Wxg, const float* __restrict__ Whg,
                               const float* __restrict__ Wxc, const float* __restrict__ Whc)
{
    const int tid    = blockIdx.x * blockDim.x + threadIdx.x;
    const int stride = gridDim.x * blockDim.x;
    const float4* wx4 = (const float4*)Wxg;
    const float4* wh4 = (const float4*)Whg;
    for (int e = tid; e < 9*60*12; e += stride) {
        int th   = e % 3;
        int gate = (e/3) & 3;
        int ic   = (e/12) % 60;
        int k    = e / 720;
        float4 v = (ic < 48) ? wx4[(k*48 + ic)*12 + gate*3 + th]
                             : wh4[(k*12 + (ic - 48))*12 + gate*3 + th];
        ((float4*)g_wg)[((k*60 + ic)*3 + th)*4 + gate] = v;
    }
    const float4* cx4 = (const float4*)Wxc;
    const float4* ch4 = (const float4*)Whc;
    for (int e = tid; e < 9*36*12; e += stride) {
        int th   = e % 3;
        int gate = (e/3) & 3;
        int ic   = (e/12) % 36;
        int k    = e / 432;
        float4 v = (ic < 24) ? cx4[(k*24 + ic)*12 + gate*3 + th]
                             : ch4[(k*12 + (ic - 24))*12 + gate*3 + th];
        ((float4*)g_wc)[((k*36 + ic)*3 + th)*4 + gate] = v;
    }
}

// ==========================================================================
// Delta kernel: Z += conv(new_slab - old_slab, Wx-chunk) for the 4 batches
// whose class view changed at step tprev. Grid (8,16): blockIdx.x = row-tile,
// blockIdx.y -> (batch quarter = by&3, chunk = by>>2). 768 threads, R11 tile.
// Must run BEFORE cls(t) (which recycles the old slab).
// ==========================================================================
#define D_SW   (9*12*48)            // 5184 floats (one 12-ic chunk)
#define D_SIN  (12*660)
#define D_SMEM_BYTES ((D_SW + D_SIN)*4)

__global__ __launch_bounds__(768, 1)
void delta_kernel(const int* __restrict__ cids, int tprev)
{
    extern __shared__ float smem[];
    float* sW  = smem;          // [9][12][3][16]
    float* sIn = smem + D_SW;   // [12][660]

    const int tid = threadIdx.x;
    const int tx  = tid & 63;
    const int rg  = (tid >> 6) & 3;
    const int th  = tid >> 8;
    const int cid = __ldg(cids + tprev);
    const int batch = cid*4 + (blockIdx.y & 3);
    const int chunk = blockIdx.y >> 2;
    const int y0  = blockIdx.x * 8;

    const float* news = g_slabs[g_wslab[tprev]];
    const float* olds = g_slabs[g_rslab[tprev*4 + cid]];

    // Stage this chunk's weights: 12 ic x 48 contiguous per tap
    for (int k = 0; k < 9; ++k) {
        const float4* s4 = (const float4*)(g_wg + (k*60 + chunk*12)*48);
        float4*       d4 = (float4*)(sW + k*576);
        if (tid < 144) d4[tid] = s4[tid];
    }

    // Stage diff tile (transposed to channel-major)
    #pragma unroll 1
    for (int e = tid; e < 1980; e += 768) {
        int px = e / 3;
        int q  = e - px*3;
        int yy = px / 66;
        int xx = px - yy*66;
        int gy = y0 + yy - 1;
        int gx = xx - 1;
        float4 v = make_float4(0.f, 0.f, 0.f, 0.f);
        if ((unsigned)gy < 64u && (unsigned)gx < 64u) {
            size_t off = (size_t)((batch & 3)*4096 + gy*64 + gx)*48 + chunk*12 + q*4;
            float4 a = *(const float4*)(news + off);
            float4 o = *(const float4*)(olds + off);
            v = make_float4(a.x - o.x, a.y - o.y, a.z - o.z, a.w - o.w);
        }
        sIn[(q*4 + 0)*660 + px] = v.x;
        sIn[(q*4 + 1)*660 + px] = v.y;
        sIn[(q*4 + 2)*660 + px] = v.z;
        sIn[(q*4 + 3)*660 + px] = v.w;
    }
    __syncthreads();

    ull acc0[8], acc1[8];
    #pragma unroll
    for (int p = 0; p < 8; ++p) { acc0[p] = 0ull; acc1[p] = 0ull; }

    #pragma unroll 1
    for (int k = 0; k < 9; ++k) {
        const int ky = k / 3;
        const int kx = k - ky*3;
        conv12t(sW + k*576 + th*16,
                sIn + (rg*2 + ky)*66 + tx + kx,
                acc0, acc1);
    }

    // Accumulate into Z (atomic: 4 chunk-CTAs share each pixel)
    #pragma unroll
    for (int r = 0; r < 2; ++r) {
        ull* accr = r ? acc1 : acc0;
        const int gy   = y0 + rg*2 + r;
        const int pidx = (batch*64 + gy)*64 + tx;
        float* zp = g_Z + (size_t)pidx*48 + th*16;
        #pragma unroll
        for (int p = 0; p < 8; ++p) {
            float2 v = unpack2(accr[p]);
            atomicAdd(zp + 2*p,     v.x);
            atomicAdd(zp + 2*p + 1, v.y);
        }
    }
}

// ==========================================================================
// General cell (incremental): gates = Z (cached class conv) + conv(genh, Wh)
// + bias. Only ONE conv chunk. Grid (8,16), 768 threads, R11 tile/epilogue.
// ==========================================================================
#define G_SW   (9*12*48)            // 5184 floats (Wh chunk, view ic 48..59)
#define G_SIN  (12*660)
#define G_SMEM_BYTES ((G_SW + G_SIN + 48)*4)

__global__ __launch_bounds__(768, 1)
void gen_cell_kernel(const float* __restrict__ bias, int t, int par)
{
    extern __shared__ float smem[];
    float* sW  = smem;
    float* sIn = smem + G_SW;
    float* sB  = smem + G_SW + G_SIN;

    const int tid = threadIdx.x;
    const int tx  = tid & 63;
    const int rg  = (tid >> 6) & 3;
    const int th  = tid >> 8;
    const int b   = blockIdx.y;
    const int y0  = blockIdx.x * 8;

    const float* genh_in  = g_genh[par];
    float*       genh_out = g_genh[par ^ 1];

    // Stage Wh chunk (view ic 48..59)
    for (int k = 0; k < 9; ++k) {
        const float4* s4 = (const float4*)(g_wg + (k*60 + 48)*48);
        float4*       d4 = (float4*)(sW + k*576);
        if (tid < 144) d4[tid] = s4[tid];
    }
    if (tid < 12) ((float4*)sB)[tid] = ((const float4*)bias)[tid];

    // Stage genh tile (transposed)
    #pragma unroll 1
    for (int e = tid; e < 1980; e += 768) {
        int px = e / 3;
        int q  = e - px*3;
        int yy = px / 66;
        int xx = px - yy*66;
        int gy = y0 + yy - 1;
        int gx = xx - 1;
        float4 v = make_float4(0.f, 0.f, 0.f, 0.f);
        if ((unsigned)gy < 64u && (unsigned)gx < 64u) {
            int pidx = (b*64 + gy)*64 + gx;
            v = *(const float4*)(genh_in + (size_t)pidx*12 + q*4);
        }
        sIn[(q*4 + 0)*660 + px] = v.x;
        sIn[(q*4 + 1)*660 + px] = v.y;
        sIn[(q*4 + 2)*660 + px] = v.z;
        sIn[(q*4 + 3)*660 + px] = v.w;
    }

    // Init accumulators from cached Z (same reordered channel order)
    ull acc0[8], acc1[8];
    {
        const int pidx0 = (b*64 + y0 + rg*2)*64 + tx;
        const float4* z0 = (const float4*)(g_Z + (size_t)pidx0*48 + th*16);
        const float4* z1 = (const float4*)(g_Z + (size_t)(pidx0 + 64)*48 + th*16);
        #pragma unroll
        for (int p2 = 0; p2 < 4; ++p2) {
            float4 v0 = z0[p2];
            float4 v1 = z1[p2];
            acc0[2*p2]   = packpair(v0.x, v0.y);
            acc0[2*p2+1] = packpair(v0.z, v0.w);
            acc1[2*p2]   = packpair(v1.x, v1.y);
            acc1[2*p2+1] = packpair(v1.z, v1.w);
        }
    }
    __syncthreads();

    #pragma unroll 1
    for (int k = 0; k < 9; ++k) {
        const int ky = k / 3;
        const int kx = k - ky*3;
        conv12t(sW + k*576 + th*16,
                sIn + (rg*2 + ky)*66 + tx + kx,
                acc0, acc1);
    }

    // Local LSTM epilogue: channels th*4..th*4+3 of all gates
    #pragma unroll
    for (int r = 0; r < 2; ++r) {
        ull* accr = r ? acc1 : acc0;
        float z[16];
        #pragma unroll
        for (int p = 0; p < 8; ++p) {
            float2 v = unpack2(accr[p]);
            z[2*p] = v.x; z[2*p+1] = v.y;
        }
        const int gy  = y0 + rg*2 + r;
        const int idx = ((b*64 + gy)*64 + tx)*12 + th*4;
        float4 c4 = *(const float4*)(g_genc + idx);
        float4 h4;
        float* cf = (float*)&c4;
        float* hf = (float*)&h4;
        #pragma unroll
        for (int j = 0; j < 4; ++j) {
            float zi = z[j]      + sB[th*4 + j];
            float zf = z[4 + j]  + sB[12 + th*4 + j];
            float zg = z[8 + j]  + sB[24 + th*4 + j];
            float zo = z[12 + j] + sB[36 + th*4 + j];
            float fi = hsig(zi), ff = hsig(zf), fo = hsig(zo);
            float cn = ff * cf[j] + fi * tanhf(zg);
            cf[j] = cn;
            hf[j] = fo * tanhf(cn);
        }
        *(float4*)(g_genc + idx)   = c4;
        *(float4*)(genh_out + idx) = h4;
    }
}

// ==========================================================================
// Class cell (R11-verbatim): 36 in-ch = 3 chunks of 12 (frame, fresh gen_h,
// class_h[cid]). Writes h_new into slab wslab[t]; accumulates out.
// ==========================================================================
#define B_SW   (9*36*48)            // 15552 floats
#define B_SIN  (12*660)
#define B_SMEM_BYTES ((B_SW + B_SIN + 48)*4)

__device__ __forceinline__ float4 ldsrc_cls(const float* __restrict__ frame,
                                            const float* __restrict__ genh_new,
                                            const float* __restrict__ chh,
                                            int ch, int pidx, int q, bool ok)
{
    if (!ok) return make_float4(0.f, 0.f, 0.f, 0.f);
    const float* src = (ch == 0) ? frame + (size_t)(pidx & 4095)*12
                     : (ch == 1) ? genh_new + (size_t)pidx*12
                                 : chh + (size_t)pidx*12;
    return *(const float4*)(src + q*4);
}

__global__ __launch_bounds__(768, 1)
void cls_cell_kernel(const float* __restrict__ x, const int* __restrict__ class_ids,
                     const float* __restrict__ bias, int t, int par,
                     float* __restrict__ out)
{
    extern __shared__ float smem[];
    float* sW  = smem;
    float* sIn = smem + B_SW;
    float* sB  = smem + B_SW + B_SIN;

    const int tid = threadIdx.x;
    const int tx  = tid & 63;
    const int rg  = (tid >> 6) & 3;
    const int th  = tid >> 8;
    const int b   = blockIdx.y;
    const int y0  = blockIdx.x * 8;
    const int cid = __ldg(class_ids + t);

    const float* genh_new = g_genh[par ^ 1];
    const float* chh      = g_slabs[g_rslab[t*4 + cid]];
    float*       hnew     = g_slabs[g_wslab[t]];
    const float* frame    = x + (size_t)(b*NTT + t)*4096*12;

    {
        const float4* s4 = (const float4*)g_wc;
        float4*       d4 = (float4*)sW;
        #pragma unroll
        for (int i = 0; i < 6; ++i) {
            int e = tid + i*768;
            if (e < 3888) d4[e] = s4[e];
        }
    }
    if (tid < 12) ((float4*)sB)[tid] = ((const float4*)bias)[tid];

    int ppx[3], pq[3], ppidx[3];
    bool pok[3], pinr[3];
    #pragma unroll
    for (int i = 0; i < 3; ++i) {
        int e  = tid + i*768;
        bool inr = e < 1980;
        int px = e/3, q = e - px*3;
        int yy = px/66, xx = px - yy*66;
        int gy = y0 + yy - 1, gx = xx - 1;
        bool inb = inr && (unsigned)gy < 64u && (unsigned)gx < 64u;
        ppx[i] = px; pq[i] = q;
        ppidx[i] = inb ? ((b*64 + gy)*64 + gx) : 0;
        pok[i] = inb; pinr[i] = inr;
    }

    ull acc0[8], acc1[8];
    #pragma unroll
    for (int p = 0; p < 8; ++p) { acc0[p] = 0ull; acc1[p] = 0ull; }

    float4 pf[3];
    #pragma unroll
    for (int i = 0; i < 3; ++i)
        pf[i] = ldsrc_cls(frame, genh_new, chh, 0, ppidx[i], pq[i], pok[i]);

    #pragma unroll 1
    for (int ch = 0; ch < 3; ++ch) {
        __syncthreads();
        #pragma unroll
        for (int i = 0; i < 3; ++i) {
            if (pinr[i]) {
                int base = pq[i]*4*660 + ppx[i];
                sIn[base]        = pf[i].x;
                sIn[base +  660] = pf[i].y;
                sIn[base + 1320] = pf[i].z;
                sIn[base + 1980] = pf[i].w;
            }
        }
        __syncthreads();
        if (ch < 2) {
            #pragma unroll
            for (int i = 0; i < 3; ++i)
                pf[i] = ldsrc_cls(frame, genh_new, chh, ch + 1, ppidx[i], pq[i], pok[i]);
        }

        #pragma unroll 1
        for (int k = 0; k < 9; ++k) {
            const int ky = k / 3;
            const int kx = k - ky*3;
            conv12t(sW + ((k*36 + ch*12)*3 + th)*16,
                    sIn + (rg*2 + ky)*66 + tx + kx,
                    acc0, acc1);
        }
    }

    float* chc = g_class_c + (size_t)cid * SSLICE;

    #pragma unroll
    for (int r = 0; r < 2; ++r) {
        ull* accr = r ? acc1 : acc0;
        float z[16];
        #pragma unroll
        for (int p = 0; p < 8; ++p) {
            float2 v = unpack2(accr[p]);
            z[2*p] = v.x; z[2*p+1] = v.y;
        }
        const int gy  = y0 + rg*2 + r;
        const int idx = ((b*64 + gy)*64 + tx)*12 + th*4;
        float4 c4 = *(const float4*)(chc + idx);
        float4 o4 = *(const float4*)(out + idx);
        float4 h4;
        float* cf = (float*)&c4;
        float* hf = (float*)&h4;
        float* of = (float*)&o4;
        #pragma unroll
        for (int j = 0; j < 4; ++j) {
            float zi = z[j]      + sB[th*4 + j];
            float zf = z[4 + j]  + sB[12 + th*4 + j];
            float zg = z[8 + j]  + sB[24 + th*4 + j];
            float zo = z[12 + j] + sB[36 + th*4 + j];
            float fi = hsig(zi), ff = hsig(zf), fo = hsig(zo);
            float cn = ff * cf[j] + fi * tanhf(zg);
            float hn = fo * tanhf(cn);
            cf[j] = cn;
            hf[j] = hn;
            of[j] += hn;
        }
        *(float4*)(chc + idx)  = c4;
        *(float4*)(hnew + idx) = h4;
        *(float4*)(out + idx)  = o4;
    }
}

// --------------------------------------------------------------------------
extern "C" void kernel_launch(void* const* d_in, const int* in_sizes, int n_in,
                              void* d_out, int out_size)
{
    const float* x    = (const float*)d_in[0];
    const int*   cids = (const int*)d_in[1];
    const float* Wxg  = (const float*)d_in[2];
    const float* Whg  = (const float*)d_in[3];
    const float* bg   = (const float*)d_in[4];
    const float* Wxc  = (const float*)d_in[5];
    const float* Whc  = (const float*)d_in[6];
    const float* bc   = (const float*)d_in[7];
    float* out = (float*)d_out;

    cudaFuncSetAttribute(delta_kernel,    cudaFuncAttributeMaxDynamicSharedMemorySize, D_SMEM_BYTES);
    cudaFuncSetAttribute(gen_cell_kernel, cudaFuncAttributeMaxDynamicSharedMemorySize, G_SMEM_BYTES);
    cudaFuncSetAttribute(cls_cell_kernel, cudaFuncAttributeMaxDynamicSharedMemorySize, B_SMEM_BYTES);

    zero_kernel<<<1024, 256>>>(out, cids);
    reorder_kernel<<<64, 256>>>(Wxg, Whg, Wxc, Whc);

    for (int t = 0; t < NTT; ++t) {
        const int par = t & 1;
        if (t > 0)
            delta_kernel<<<dim3(8, 16), 768, D_SMEM_BYTES>>>(cids, t - 1);
        gen_cell_kernel<<<dim3(8, 16), 768, G_SMEM_BYTES>>>(bg, t, par);
        cls_cell_kernel<<<dim3(8, 16), 768, B_SMEM_BYTES>>>(x, cids, bc, t, par, out);
    }
}

// round 15
// speedup vs baseline: 2.6866x; 1.0894x over previous
#include <cuda_runtime.h>

// Problem dims
#define NCC 4
#define BSZ 16
#define NTT 32
#define SSLICE (BSZ*64*64*12)   // 786432 floats per (BS,H,W,OC) slab

// Persistent device state
__device__ __align__(16) float g_slabs[5][SSLICE];
__device__ __align__(16) float g_class_c[NCC*SSLICE];
__device__ __align__(16) float g_genh[2][SSLICE];
__device__ __align__(16) float g_genc[SSLICE];

// Cached class-conv pre-activations: Z[pixel][48] = conv(class_view, Wx_g),
// stored in the reordered [third][gate][4] channel order (matches acc layout).
__device__ __align__(16) float g_Z[4*SSLICE];

// Reordered weights: [k][ic][third][gate][4]; third th owns oc channels
// gate*12 + th*4 .. +3 of every gate.
__device__ __align__(16) float g_wg[9*60*48];
__device__ __align__(16) float g_wc[9*36*48];

// Slab schedule: g_rslab[t*4+c] = slab holding class_h[c] at start of step t;
// g_wslab[t] = slab step t's cls writes h_new into.
__device__ int g_rslab[NTT*NCC];
__device__ int g_wslab[NTT];

__device__ __forceinline__ float hsig(float x) {
    return fminf(fmaxf(x + 3.0f, 0.0f), 6.0f) * (1.0f/6.0f);
}

typedef unsigned long long ull;

__device__ __forceinline__ ull pack2(float x) {
    ull r;
    unsigned int xi = __float_as_uint(x);
    asm("mov.b64 %0, {%1, %1};" : "=l"(r) : "r"(xi));
    return r;
}
__device__ __forceinline__ ull packpair(float a, float b) {
    ull r;
    asm("mov.b64 %0, {%1, %2};" : "=l"(r) : "f"(a), "f"(b));
    return r;
}
__device__ __forceinline__ void ffma2(ull& d, ull a, ull b) {
    asm("fma.rn.f32x2 %0, %1, %2, %0;" : "+l"(d) : "l"(a), "l"(b));
}
__device__ __forceinline__ float2 unpack2(ull v) {
    float2 r;
    asm("mov.b64 {%0, %1}, %2;" : "=f"(r.x), "=f"(r.y) : "l"(v));
    return r;
}

// --------------------------------------------------------------------------
// 12-channel conv tap, 16-oc third per thread. Channel stride 48 floats =
// 12 ulonglong2; this thread's 16 floats contiguous (4 u2).
// xb channel-major: channel icc at xb[icc*660], next row +66.
// --------------------------------------------------------------------------
__device__ __forceinline__ void conv12t(const float* __restrict__ sWk,
                                        const float* __restrict__ xb,
                                        ull* __restrict__ acc0,
                                        ull* __restrict__ acc1)
{
    const ulonglong2* wp = (const ulonglong2*)sWk;
    #pragma unroll 2
    for (int icc = 0; icc < 12; ++icc) {
        ull xp0 = pack2(xb[icc*660]);
        ull xp1 = pack2(xb[icc*660 + 66]);
        const ulonglong2* w = wp + icc*12;   // 48-float channel stride
        #pragma unroll
        for (int p = 0; p < 4; ++p) {
            ulonglong2 ww = w[p];
            ffma2(acc0[2*p],   xp0, ww.x);
            ffma2(acc0[2*p+1], xp0, ww.y);
            ffma2(acc1[2*p],   xp1, ww.x);
            ffma2(acc1[2*p+1], xp1, ww.y);
        }
    }
}

// --------------------------------------------------------------------------
__global__ void zero_kernel(float* __restrict__ out, const int* __restrict__ cids)
{
    const int tid    = blockIdx.x * blockDim.x + threadIdx.x;
    const int stride = gridDim.x * blockDim.x;
    for (int i = tid; i < 5*SSLICE; i += stride)
        (&g_slabs[0][0])[i] = 0.0f;
    for (int i = tid; i < 4*SSLICE; i += stride) {
        g_class_c[i] = 0.0f;
        g_Z[i]       = 0.0f;
    }
    for (int i = tid; i < SSLICE; i += stride) {
        g_genh[0][i] = 0.0f;
        g_genc[i]    = 0.0f;
        out[i]       = 0.0f;
    }
    if (tid == 0) {
        int slab[NCC] = {0, 1, 2, 3};
        int spare = 4;
        for (int t = 0; t < NTT; ++t) {
            int cid = cids[t];
            #pragma unroll
            for (int c = 0; c < NCC; ++c) g_rslab[t*4 + c] = slab[c];
            g_wslab[t] = spare;
            int old = slab[cid];
            slab[cid] = spare;
            spare = old;
        }
    }
}

// --------------------------------------------------------------------------
// One-time weight reorder into [k][ic][third][gate][4] layout.
// --------------------------------------------------------------------------
__global__ void reorder_kernel(const float* __restrict__ Wxg, const float* __restrict__ Whg,
                               const float* __restrict__ Wxc, const float* __restrict__ Whc)
{
    const int tid    = blockIdx.x * blockDim.x + threadIdx.x;
    const int stride = gridDim.x * blockDim.x;
    const float4* wx4 = (const float4*)Wxg;
    const float4* wh4 = (const float4*)Whg;
    for (int e = tid; e < 9*60*12; e += stride) {
        int th   = e % 3;
        int gate = (e/3) & 3;
        int ic   = (e/12) % 60;
        int k    = e / 720;
        float4 v = (ic < 48) ? wx4[(k*48 + ic)*12 + gate*3 + th]
                             : wh4[(k*12 + (ic - 48))*12 + gate*3 + th];
        ((float4*)g_wg)[((k*60 + ic)*3 + th)*4 + gate] = v;
    }
    const float4* cx4 = (const float4*)Wxc;
    const float4* ch4 = (const float4*)Whc;
    for (int e = tid; e < 9*36*12; e += stride) {
        int th   = e % 3;
        int gate = (e/3) & 3;
        int ic   = (e/12) % 36;
        int k    = e / 432;
        float4 v = (ic < 24) ? cx4[(k*24 + ic)*12 + gate*3 + th]
                             : ch4[(k*12 + (ic - 24))*12 + gate*3 + th];
        ((float4*)g_wc)[((k*36 + ic)*3 + th)*4 + gate] = v;
    }
}

// ==========================================================================
// Delta kernel: Z += conv(new_slab - old_slab, Wx-chunk) for the 4 batches
// whose class view changed at step tprev. Grid (8,16): blockIdx.x = row-tile,
// blockIdx.y -> (batch quarter = by&3, chunk = by>>2). 768 threads.
// Z accumulation via float4 red.global (sm_90+), 8 per thread.
// ==========================================================================
#define D_SW   (9*12*48)            // 5184 floats (one 12-ic chunk)
#define D_SIN  (12*660)
#define D_SMEM_BYTES ((D_SW + D_SIN)*4)

__global__ __launch_bounds__(768, 1)
void delta_kernel(const int* __restrict__ cids, int tprev)
{
    extern __shared__ float smem[];
    float* sW  = smem;          // [9][12][3][16]
    float* sIn = smem + D_SW;   // [12][660]

    const int tid = threadIdx.x;
    const int tx  = tid & 63;
    const int rg  = (tid >> 6) & 3;
    const int th  = tid >> 8;
    const int cid = __ldg(cids + tprev);
    const int batch = cid*4 + (blockIdx.y & 3);
    const int chunk = blockIdx.y >> 2;
    const int y0  = blockIdx.x * 8;

    const float* news = g_slabs[g_wslab[tprev]];
    const float* olds = g_slabs[g_rslab[tprev*4 + cid]];

    // Stage this chunk's weights: 12 ic x 48 contiguous per tap
    for (int k = 0; k < 9; ++k) {
        const float4* s4 = (const float4*)(g_wg + (k*60 + chunk*12)*48);
        float4*       d4 = (float4*)(sW + k*576);
        if (tid < 144) d4[tid] = s4[tid];
    }

    // Stage diff tile (transposed to channel-major)
    #pragma unroll 1
    for (int e = tid; e < 1980; e += 768) {
        int px = e / 3;
        int q  = e - px*3;
        int yy = px / 66;
        int xx = px - yy*66;
        int gy = y0 + yy - 1;
        int gx = xx - 1;
        float4 v = make_float4(0.f, 0.f, 0.f, 0.f);
        if ((unsigned)gy < 64u && (unsigned)gx < 64u) {
            size_t off = (size_t)((batch & 3)*4096 + gy*64 + gx)*48 + chunk*12 + q*4;
            float4 a = *(const float4*)(news + off);
            float4 o = *(const float4*)(olds + off);
            v = make_float4(a.x - o.x, a.y - o.y, a.z - o.z, a.w - o.w);
        }
        sIn[(q*4 + 0)*660 + px] = v.x;
        sIn[(q*4 + 1)*660 + px] = v.y;
        sIn[(q*4 + 2)*660 + px] = v.z;
        sIn[(q*4 + 3)*660 + px] = v.w;
    }
    __syncthreads();

    ull acc0[8], acc1[8];
    #pragma unroll
    for (int p = 0; p < 8; ++p) { acc0[p] = 0ull; acc1[p] = 0ull; }

    #pragma unroll 1
    for (int k = 0; k < 9; ++k) {
        const int ky = k / 3;
        const int kx = k - ky*3;
        conv12t(sW + k*576 + th*16,
                sIn + (rg*2 + ky)*66 + tx + kx,
                acc0, acc1);
    }

    // Accumulate into Z via vector red (4 chunk-CTAs share each pixel)
    #pragma unroll
    for (int r = 0; r < 2; ++r) {
        ull* accr = r ? acc1 : acc0;
        const int gy   = y0 + rg*2 + r;
        const int pidx = (batch*64 + gy)*64 + tx;
        float4* zp = (float4*)(g_Z + (size_t)pidx*48 + th*16);
        #pragma unroll
        for (int p2 = 0; p2 < 4; ++p2) {
            float2 lo = unpack2(accr[2*p2]);
            float2 hi = unpack2(accr[2*p2+1]);
            atomicAdd(zp + p2, make_float4(lo.x, lo.y, hi.x, hi.y));
        }
    }
}

// ==========================================================================
// General cell (incremental): gates = Z (cached class conv) + conv(genh, Wh)
// + bias. Only ONE conv chunk. Grid (8,16), 768 threads.
// ==========================================================================
#define G_SW   (9*12*48)            // 5184 floats (Wh chunk, view ic 48..59)
#define G_SIN  (12*660)
#define G_SMEM_BYTES ((G_SW + G_SIN + 48)*4)

__global__ __launch_bounds__(768, 1)
void gen_cell_kernel(const float* __restrict__ bias, int t, int par)
{
    extern __shared__ float smem[];
    float* sW  = smem;
    float* sIn = smem + G_SW;
    float* sB  = smem + G_SW + G_SIN;

    const int tid = threadIdx.x;
    const int tx  = tid & 63;
    const int rg  = (tid >> 6) & 3;
    const int th  = tid >> 8;
    const int b   = blockIdx.y;
    const int y0  = blockIdx.x * 8;

    const float* genh_in  = g_genh[par];
    float*       genh_out = g_genh[par ^ 1];

    // Stage Wh chunk (view ic 48..59)
    for (int k = 0; k < 9; ++k) {
        const float4* s4 = (const float4*)(g_wg + (k*60 + 48)*48);
        float4*       d4 = (float4*)(sW + k*576);
        if (tid < 144) d4[tid] = s4[tid];
    }
    if (tid < 12) ((float4*)sB)[tid] = ((const float4*)bias)[tid];

    // Stage genh tile (transposed)
    #pragma unroll 1
    for (int e = tid; e < 1980; e += 768) {
        int px = e / 3;
        int q  = e - px*3;
        int yy = px / 66;
        int xx = px - yy*66;
        int gy = y0 + yy - 1;
        int gx = xx - 1;
        float4 v = make_float4(0.f, 0.f, 0.f, 0.f);
        if ((unsigned)gy < 64u && (unsigned)gx < 64u) {
            int pidx = (b*64 + gy)*64 + gx;
            v = *(const float4*)(genh_in + (size_t)pidx*12 + q*4);
        }
        sIn[(q*4 + 0)*660 + px] = v.x;
        sIn[(q*4 + 1)*660 + px] = v.y;
        sIn[(q*4 + 2)*660 + px] = v.z;
        sIn[(q*4 + 3)*660 + px] = v.w;
    }

    // Init accumulators from cached Z (same reordered channel order)
    ull acc0[8], acc1[8];
    {
        const int pidx0 = (b*64 + y0 + rg*2)*64 + tx;
        const float4* z0 = (const float4*)(g_Z + (size_t)pidx0*48 + th*16);
        const float4* z1 = (const float4*)(g_Z + (size_t)(pidx0 + 64)*48 + th*16);
        #pragma unroll
        for (int p2 = 0; p2 < 4; ++p2) {
            float4 v0 = z0[p2];
            float4 v1 = z1[p2];
            acc0[2*p2]   = packpair(v0.x, v0.y);
            acc0[2*p2+1] = packpair(v0.z, v0.w);
            acc1[2*p2]   = packpair(v1.x, v1.y);
            acc1[2*p2+1] = packpair(v1.z, v1.w);
        }
    }
    __syncthreads();

    #pragma unroll 1
    for (int k = 0; k < 9; ++k) {
        const int ky = k / 3;
        const int kx = k - ky*3;
        conv12t(sW + k*576 + th*16,
                sIn + (rg*2 + ky)*66 + tx + kx,
                acc0, acc1);
    }

    // Local LSTM epilogue: channels th*4..th*4+3 of all gates
    #pragma unroll
    for (int r = 0; r < 2; ++r) {
        ull* accr = r ? acc1 : acc0;
        float z[16];
        #pragma unroll
        for (int p = 0; p < 8; ++p) {
            float2 v = unpack2(accr[p]);
            z[2*p] = v.x; z[2*p+1] = v.y;
        }
        const int gy  = y0 + rg*2 + r;
        const int idx = ((b*64 + gy)*64 + tx)*12 + th*4;
        float4 c4 = *(const float4*)(g_genc + idx);
        float4 h4;
        float* cf = (float*)&c4;
        float* hf = (float*)&h4;
        #pragma unroll
        for (int j = 0; j < 4; ++j) {
            float zi = z[j]      + sB[th*4 + j];
            float zf = z[4 + j]  + sB[12 + th*4 + j];
            float zg = z[8 + j]  + sB[24 + th*4 + j];
            float zo = z[12 + j] + sB[36 + th*4 + j];
            float fi = hsig(zi), ff = hsig(zf), fo = hsig(zo);
            float cn = ff * cf[j] + fi * tanhf(zg);
            cf[j] = cn;
            hf[j] = fo * tanhf(cn);
        }
        *(float4*)(g_genc + idx)   = c4;
        *(float4*)(genh_out + idx) = h4;
    }
}

// ==========================================================================
// Class cell: 36 in-ch = 3 chunks of 12 (frame, fresh gen_h, class_h[cid]).
// Double-buffered input staging: ONE sync per chunk. Writes h_new into
// slab wslab[t]; accumulates out.
// ==========================================================================
#define B_SW   (9*36*48)            // 15552 floats
#define B_SIN  (12*660)             // per buffer
#define B_SMEM_BYTES ((B_SW + 2*B_SIN + 48)*4)

__device__ __forceinline__ float4 ldsrc_cls(const float* __restrict__ frame,
                                            const float* __restrict__ genh_new,
                                            const float* __restrict__ chh,
                                            int ch, int pidx, int q, bool ok)
{
    if (!ok) return make_float4(0.f, 0.f, 0.f, 0.f);
    const float* src = (ch == 0) ? frame + (size_t)(pidx & 4095)*12
                     : (ch == 1) ? genh_new + (size_t)pidx*12
                                 : chh + (size_t)pidx*12;
    return *(const float4*)(src + q*4);
}

__global__ __launch_bounds__(768, 1)
void cls_cell_kernel(const float* __restrict__ x, const int* __restrict__ class_ids,
                     const float* __restrict__ bias, int t, int par,
                     float* __restrict__ out)
{
    extern __shared__ float smem[];
    float* sW   = smem;
    float* sIn0 = smem + B_SW;
    float* sIn1 = smem + B_SW + B_SIN;
    float* sB   = smem + B_SW + 2*B_SIN;

    const int tid = threadIdx.x;
    const int tx  = tid & 63;
    const int rg  = (tid >> 6) & 3;
    const int th  = tid >> 8;
    const int b   = blockIdx.y;
    const int y0  = blockIdx.x * 8;
    const int cid = __ldg(class_ids + t);

    const float* genh_new = g_genh[par ^ 1];
    const float* chh      = g_slabs[g_rslab[t*4 + cid]];
    float*       hnew     = g_slabs[g_wslab[t]];
    const float* frame    = x + (size_t)(b*NTT + t)*4096*12;

    {
        const float4* s4 = (const float4*)g_wc;
        float4*       d4 = (float4*)sW;
        #pragma unroll
        for (int i = 0; i < 6; ++i) {
            int e = tid + i*768;
            if (e < 3888) d4[e] = s4[e];
        }
    }
    if (tid < 12) ((float4*)sB)[tid] = ((const float4*)bias)[tid];

    int ppx[3], pq[3], ppidx[3];
    bool pok[3], pinr[3];
    #pragma unroll
    for (int i = 0; i < 3; ++i) {
        int e  = tid + i*768;
        bool inr = e < 1980;
        int px = e/3, q = e - px*3;
        int yy = px/66, xx = px - yy*66;
        int gy = y0 + yy - 1, gx = xx - 1;
        bool inb = inr && (unsigned)gy < 64u && (unsigned)gx < 64u;
        ppx[i] = px; pq[i] = q;
        ppidx[i] = inb ? ((b*64 + gy)*64 + gx) : 0;
        pok[i] = inb; pinr[i] = inr;
    }

    ull acc0[8], acc1[8];
    #pragma unroll
    for (int p = 0; p < 8; ++p) { acc0[p] = 0ull; acc1[p] = 0ull; }

    float4 pf[3];
    #pragma unroll
    for (int i = 0; i < 3; ++i)
        pf[i] = ldsrc_cls(frame, genh_new, chh, 0, ppidx[i], pq[i], pok[i]);

    #pragma unroll 1
    for (int ch = 0; ch < 3; ++ch) {
        float* buf = (ch & 1) ? sIn1 : sIn0;
        // Store prefetched chunk into this chunk's buffer (no prior sync
        // needed: previous conv read the OTHER buffer).
        #pragma unroll
        for (int i = 0; i < 3; ++i) {
            if (pinr[i]) {
                int base = pq[i]*4*660 + ppx[i];
                buf[base]        = pf[i].x;
                buf[base +  660] = pf[i].y;
                buf[base + 1320] = pf[i].z;
                buf[base + 1980] = pf[i].w;
            }
        }
        __syncthreads();
        if (ch < 2) {
            #pragma unroll
            for (int i = 0; i < 3; ++i)
                pf[i] = ldsrc_cls(frame, genh_new, chh, ch + 1, ppidx[i], pq[i], pok[i]);
        }

        #pragma unroll 1
        for (int k = 0; k < 9; ++k) {
            const int ky = k / 3;
            const int kx = k - ky*3;
            conv12t(sW + ((k*36 + ch*12)*3 + th)*16,
                    buf + (rg*2 + ky)*66 + tx + kx,
                    acc0, acc1);
        }
    }

    float* chc = g_class_c + (size_t)cid * SSLICE;

    #pragma unroll
    for (int r = 0; r < 2; ++r) {
        ull* accr = r ? acc1 : acc0;
        float z[16];
        #pragma unroll
        for (int p = 0; p < 8; ++p) {
            float2 v = unpack2(accr[p]);
            z[2*p] = v.x; z[2*p+1] = v.y;
        }
        const int gy  = y0 + rg*2 + r;
        const int idx = ((b*64 + gy)*64 + tx)*12 + th*4;
        float4 c4 = *(const float4*)(chc + idx);
        float4 o4 = *(const float4*)(out + idx);
        float4 h4;
        float* cf = (float*)&c4;
        float* hf = (float*)&h4;
        float* of = (float*)&o4;
        #pragma unroll
        for (int j = 0; j < 4; ++j) {
            float zi = z[j]      + sB[th*4 + j];
            float zf = z[4 + j]  + sB[12 + th*4 + j];
            float zg = z[8 + j]  + sB[24 + th*4 + j];
            float zo = z[12 + j] + sB[36 + th*4 + j];
            float fi = hsig(zi), ff = hsig(zf), fo = hsig(zo);
            float cn = ff * cf[j] + fi * tanhf(zg);
            float hn = fo * tanhf(cn);
            cf[j] = cn;
            hf[j] = hn;
            of[j] += hn;
        }
        *(float4*)(chc + idx)  = c4;
        *(float4*)(hnew + idx) = h4;
        *(float4*)(out + idx)  = o4;
    }
}

// --------------------------------------------------------------------------
extern "C" void kernel_launch(void* const* d_in, const int* in_sizes, int n_in,
                              void* d_out, int out_size)
{
    const float* x    = (const float*)d_in[0];
    const int*   cids = (const int*)d_in[1];
    const float* Wxg  = (const float*)d_in[2];
    const float* Whg  = (const float*)d_in[3];
    const float* bg   = (const float*)d_in[4];
    const float* Wxc  = (const float*)d_in[5];
    const float* Whc  = (const float*)d_in[6];
    const float* bc   = (const float*)d_in[7];
    float* out = (float*)d_out;

    cudaFuncSetAttribute(delta_kernel,    cudaFuncAttributeMaxDynamicSharedMemorySize, D_SMEM_BYTES);
    cudaFuncSetAttribute(gen_cell_kernel, cudaFuncAttributeMaxDynamicSharedMemorySize, G_SMEM_BYTES);
    cudaFuncSetAttribute(cls_cell_kernel, cudaFuncAttributeMaxDynamicSharedMemorySize, B_SMEM_BYTES);

    zero_kernel<<<1024, 256>>>(out, cids);
    reorder_kernel<<<64, 256>>>(Wxg, Whg, Wxc, Whc);

    for (int t = 0; t < NTT; ++t) {
        const int par = t & 1;
        if (t > 0)
            delta_kernel<<<dim3(8, 16), 768, D_SMEM_BYTES>>>(cids, t - 1);
        gen_cell_kernel<<<dim3(8, 16), 768, G_SMEM_BYTES>>>(bg, t, par);
        cls_cell_kernel<<<dim3(8, 16), 768, B_SMEM_BYTES>>>(x, cids, bc, t, par, out);
    }
}

// round 16
// speedup vs baseline: 2.9590x; 1.1014x over previous
#include <cuda_runtime.h>

// Problem dims
#define NCC 4
#define BSZ 16
#define NTT 32
#define SSLICE (BSZ*64*64*12)   // 786432 floats per (BS,H,W,OC) slab

// Persistent device state
__device__ __align__(16) float g_slabs[5][SSLICE];
__device__ __align__(16) float g_class_c[NCC*SSLICE];
__device__ __align__(16) float g_genh[2][SSLICE];
__device__ __align__(16) float g_genc[SSLICE];

// Cached class-conv pre-activations: Z[pixel][48] = conv(class_view, Wx_g),
// stored in the reordered [third][gate][4] channel order (matches acc layout).
__device__ __align__(16) float g_Z[4*SSLICE];

// Reordered weights: [k][ic][third][gate][4]; third th owns oc channels
// gate*12 + th*4 .. +3 of every gate.
__device__ __align__(16) float g_wg[9*60*48];
__device__ __align__(16) float g_wc[9*36*48];

// Slab schedule: g_rslab[t*4+c] = slab holding class_h[c] at start of step t;
// g_wslab[t] = slab step t's cls writes h_new into.
__device__ int g_rslab[NTT*NCC];
__device__ int g_wslab[NTT];

__device__ __forceinline__ float hsig(float x) {
    return fminf(fmaxf(x + 3.0f, 0.0f), 6.0f) * (1.0f/6.0f);
}

typedef unsigned long long ull;

__device__ __forceinline__ ull pack2(float x) {
    ull r;
    unsigned int xi = __float_as_uint(x);
    asm("mov.b64 %0, {%1, %1};" : "=l"(r) : "r"(xi));
    return r;
}
__device__ __forceinline__ ull packpair(float a, float b) {
    ull r;
    asm("mov.b64 %0, {%1, %2};" : "=l"(r) : "f"(a), "f"(b));
    return r;
}
__device__ __forceinline__ void ffma2(ull& d, ull a, ull b) {
    asm("fma.rn.f32x2 %0, %1, %2, %0;" : "+l"(d) : "l"(a), "l"(b));
}
__device__ __forceinline__ float2 unpack2(ull v) {
    float2 r;
    asm("mov.b64 {%0, %1}, %2;" : "=f"(r.x), "=f"(r.y) : "l"(v));
    return r;
}

// --------------------------------------------------------------------------
// 12-channel conv tap, 16-oc third per thread. Channel stride 48 floats =
// 12 ulonglong2; this thread's 16 floats contiguous (4 u2).
// FULLY UNROLLED: every LDS gets a compile-time immediate offset, removing
// the per-channel IMAD address chains (alu-pipe relief).
// xb channel-major: channel icc at xb[icc*660], next row +66.
// --------------------------------------------------------------------------
__device__ __forceinline__ void conv12t(const float* __restrict__ sWk,
                                        const float* __restrict__ xb,
                                        ull* __restrict__ acc0,
                                        ull* __restrict__ acc1)
{
    const ulonglong2* wp = (const ulonglong2*)sWk;
    #pragma unroll
    for (int icc = 0; icc < 12; ++icc) {
        ull xp0 = pack2(xb[icc*660]);
        ull xp1 = pack2(xb[icc*660 + 66]);
        const ulonglong2* w = wp + icc*12;   // 48-float channel stride
        #pragma unroll
        for (int p = 0; p < 4; ++p) {
            ulonglong2 ww = w[p];
            ffma2(acc0[2*p],   xp0, ww.x);
            ffma2(acc0[2*p+1], xp0, ww.y);
            ffma2(acc1[2*p],   xp1, ww.x);
            ffma2(acc1[2*p+1], xp1, ww.y);
        }
    }
}

// --------------------------------------------------------------------------
__global__ void zero_kernel(float* __restrict__ out, const int* __restrict__ cids)
{
    const int tid    = blockIdx.x * blockDim.x + threadIdx.x;
    const int stride = gridDim.x * blockDim.x;
    for (int i = tid; i < 5*SSLICE; i += stride)
        (&g_slabs[0][0])[i] = 0.0f;
    for (int i = tid; i < 4*SSLICE; i += stride) {
        g_class_c[i] = 0.0f;
        g_Z[i]       = 0.0f;
    }
    for (int i = tid; i < SSLICE; i += stride) {
        g_genh[0][i] = 0.0f;
        g_genc[i]    = 0.0f;
        out[i]       = 0.0f;
    }
    if (tid == 0) {
        int slab[NCC] = {0, 1, 2, 3};
        int spare = 4;
        for (int t = 0; t < NTT; ++t) {
            int cid = cids[t];
            #pragma unroll
            for (int c = 0; c < NCC; ++c) g_rslab[t*4 + c] = slab[c];
            g_wslab[t] = spare;
            int old = slab[cid];
            slab[cid] = spare;
            spare = old;
        }
    }
}

// --------------------------------------------------------------------------
// One-time weight reorder into [k][ic][third][gate][4] layout.
// --------------------------------------------------------------------------
__global__ void reorder_kernel(const float* __restrict__ Wxg, const float* __restrict__ Whg,
                               const float* __restrict__ Wxc, const float* __restrict__ Whc)
{
    const int tid    = blockIdx.x * blockDim.x + threadIdx.x;
    const int stride = gridDim.x * blockDim.x;
    const float4* wx4 = (const float4*)Wxg;
    const float4* wh4 = (const float4*)Whg;
    for (int e = tid; e < 9*60*12; e += stride) {
        int th   = e % 3;
        int gate = (e/3) & 3;
        int ic   = (e/12) % 60;
        int k    = e / 720;
        float4 v = (ic < 48) ? wx4[(k*48 + ic)*12 + gate*3 + th]
                             : wh4[(k*12 + (ic - 48))*12 + gate*3 + th];
        ((float4*)g_wg)[((k*60 + ic)*3 + th)*4 + gate] = v;
    }
    const float4* cx4 = (const float4*)Wxc;
    const float4* ch4 = (const float4*)Whc;
    for (int e = tid; e < 9*36*12; e += stride) {
        int th   = e % 3;
        int gate = (e/3) & 3;
        int ic   = (e/12) % 36;
        int k    = e / 432;
        float4 v = (ic < 24) ? cx4[(k*24 + ic)*12 + gate*3 + th]
                             : ch4[(k*12 + (ic - 24))*12 + gate*3 + th];
        ((float4*)g_wc)[((k*36 + ic)*3 + th)*4 + gate] = v;
    }
}

// ==========================================================================
// Delta kernel: Z += conv(new_slab - old_slab, Wx-chunk) for the 4 batches
// whose class view changed at step tprev. Grid (8,16): blockIdx.x = row-tile,
// blockIdx.y -> (batch quarter = by&3, chunk = by>>2). 768 threads.
// Z accumulation via float4 red.global (sm_90+), 8 per thread.
// ==========================================================================
#define D_SW   (9*12*48)            // 5184 floats (one 12-ic chunk)
#define D_SIN  (12*660)
#define D_SMEM_BYTES ((D_SW + D_SIN)*4)

__global__ __launch_bounds__(768, 1)
void delta_kernel(const int* __restrict__ cids, int tprev)
{
    extern __shared__ float smem[];
    float* sW  = smem;          // [9][12][3][16]
    float* sIn = smem + D_SW;   // [12][660]

    const int tid = threadIdx.x;
    const int tx  = tid & 63;
    const int rg  = (tid >> 6) & 3;
    const int th  = tid >> 8;
    const int cid = __ldg(cids + tprev);
    const int batch = cid*4 + (blockIdx.y & 3);
    const int chunk = blockIdx.y >> 2;
    const int y0  = blockIdx.x * 8;

    const float* news = g_slabs[g_wslab[tprev]];
    const float* olds = g_slabs[g_rslab[tprev*4 + cid]];

    // Stage this chunk's weights: 12 ic x 48 contiguous per tap
    for (int k = 0; k < 9; ++k) {
        const float4* s4 = (const float4*)(g_wg + (k*60 + chunk*12)*48);
        float4*       d4 = (float4*)(sW + k*576);
        if (tid < 144) d4[tid] = s4[tid];
    }

    // Stage diff tile (transposed to channel-major)
    #pragma unroll 1
    for (int e = tid; e < 1980; e += 768) {
        int px = e / 3;
        int q  = e - px*3;
        int yy = px / 66;
        int xx = px - yy*66;
        int gy = y0 + yy - 1;
        int gx = xx - 1;
        float4 v = make_float4(0.f, 0.f, 0.f, 0.f);
        if ((unsigned)gy < 64u && (unsigned)gx < 64u) {
            size_t off = (size_t)((batch & 3)*4096 + gy*64 + gx)*48 + chunk*12 + q*4;
            float4 a = *(const float4*)(news + off);
            float4 o = *(const float4*)(olds + off);
            v = make_float4(a.x - o.x, a.y - o.y, a.z - o.z, a.w - o.w);
        }
        sIn[(q*4 + 0)*660 + px] = v.x;
        sIn[(q*4 + 1)*660 + px] = v.y;
        sIn[(q*4 + 2)*660 + px] = v.z;
        sIn[(q*4 + 3)*660 + px] = v.w;
    }
    __syncthreads();

    ull acc0[8], acc1[8];
    #pragma unroll
    for (int p = 0; p < 8; ++p) { acc0[p] = 0ull; acc1[p] = 0ull; }

    #pragma unroll 1
    for (int k = 0; k < 9; ++k) {
        const int ky = k / 3;
        const int kx = k - ky*3;
        conv12t(sW + k*576 + th*16,
                sIn + (rg*2 + ky)*66 + tx + kx,
                acc0, acc1);
    }

    // Accumulate into Z via vector red (4 chunk-CTAs share each pixel)
    #pragma unroll
    for (int r = 0; r < 2; ++r) {
        ull* accr = r ? acc1 : acc0;
        const int gy   = y0 + rg*2 + r;
        const int pidx = (batch*64 + gy)*64 + tx;
        float4* zp = (float4*)(g_Z + (size_t)pidx*48 + th*16);
        #pragma unroll
        for (int p2 = 0; p2 < 4; ++p2) {
            float2 lo = unpack2(accr[2*p2]);
            float2 hi = unpack2(accr[2*p2+1]);
            atomicAdd(zp + p2, make_float4(lo.x, lo.y, hi.x, hi.y));
        }
    }
}

// ==========================================================================
// General cell (incremental): gates = Z (cached class conv) + conv(genh, Wh)
// + bias. Only ONE conv chunk. Grid (8,16), 768 threads.
// ==========================================================================
#define G_SW   (9*12*48)            // 5184 floats (Wh chunk, view ic 48..59)
#define G_SIN  (12*660)
#define G_SMEM_BYTES ((G_SW + G_SIN + 48)*4)

__global__ __launch_bounds__(768, 1)
void gen_cell_kernel(const float* __restrict__ bias, int t, int par)
{
    extern __shared__ float smem[];
    float* sW  = smem;
    float* sIn = smem + G_SW;
    float* sB  = smem + G_SW + G_SIN;

    const int tid = threadIdx.x;
    const int tx  = tid & 63;
    const int rg  = (tid >> 6) & 3;
    const int th  = tid >> 8;
    const int b   = blockIdx.y;
    const int y0  = blockIdx.x * 8;

    const float* genh_in  = g_genh[par];
    float*       genh_out = g_genh[par ^ 1];

    // Stage Wh chunk (view ic 48..59)
    for (int k = 0; k < 9; ++k) {
        const float4* s4 = (const float4*)(g_wg + (k*60 + 48)*48);
        float4*       d4 = (float4*)(sW + k*576);
        if (tid < 144) d4[tid] = s4[tid];
    }
    if (tid < 12) ((float4*)sB)[tid] = ((const float4*)bias)[tid];

    // Stage genh tile (transposed)
    #pragma unroll 1
    for (int e = tid; e < 1980; e += 768) {
        int px = e / 3;
        int q  = e - px*3;
        int yy = px / 66;
        int xx = px - yy*66;
        int gy = y0 + yy - 1;
        int gx = xx - 1;
        float4 v = make_float4(0.f, 0.f, 0.f, 0.f);
        if ((unsigned)gy < 64u && (unsigned)gx < 64u) {
            int pidx = (b*64 + gy)*64 + gx;
            v = *(const float4*)(genh_in + (size_t)pidx*12 + q*4);
        }
        sIn[(q*4 + 0)*660 + px] = v.x;
        sIn[(q*4 + 1)*660 + px] = v.y;
        sIn[(q*4 + 2)*660 + px] = v.z;
        sIn[(q*4 + 3)*660 + px] = v.w;
    }

    // Init accumulators from cached Z (same reordered channel order)
    ull acc0[8], acc1[8];
    {
        const int pidx0 = (b*64 + y0 + rg*2)*64 + tx;
        const float4* z0 = (const float4*)(g_Z + (size_t)pidx0*48 + th*16);
        const float4* z1 = (const float4*)(g_Z + (size_t)(pidx0 + 64)*48 + th*16);
        #pragma unroll
        for (int p2 = 0; p2 < 4; ++p2) {
            float4 v0 = z0[p2];
            float4 v1 = z1[p2];
            acc0[2*p2]   = packpair(v0.x, v0.y);
            acc0[2*p2+1] = packpair(v0.z, v0.w);
            acc1[2*p2]   = packpair(v1.x, v1.y);
            acc1[2*p2+1] = packpair(v1.z, v1.w);
        }
    }
    __syncthreads();

    #pragma unroll 1
    for (int k = 0; k < 9; ++k) {
        const int ky = k / 3;
        const int kx = k - ky*3;
        conv12t(sW + k*576 + th*16,
                sIn + (rg*2 + ky)*66 + tx + kx,
                acc0, acc1);
    }

    // Local LSTM epilogue: channels th*4..th*4+3 of all gates
    #pragma unroll
    for (int r = 0; r < 2; ++r) {
        ull* accr = r ? acc1 : acc0;
        float z[16];
        #pragma unroll
        for (int p = 0; p < 8; ++p) {
            float2 v = unpack2(accr[p]);
            z[2*p] = v.x; z[2*p+1] = v.y;
        }
        const int gy  = y0 + rg*2 + r;
        const int idx = ((b*64 + gy)*64 + tx)*12 + th*4;
        float4 c4 = *(const float4*)(g_genc + idx);
        float4 h4;
        float* cf = (float*)&c4;
        float* hf = (float*)&h4;
        #pragma unroll
        for (int j = 0; j < 4; ++j) {
            float zi = z[j]      + sB[th*4 + j];
            float zf = z[4 + j]  + sB[12 + th*4 + j];
            float zg = z[8 + j]  + sB[24 + th*4 + j];
            float zo = z[12 + j] + sB[36 + th*4 + j];
            float fi = hsig(zi), ff = hsig(zf), fo = hsig(zo);
            float cn = ff * cf[j] + fi * tanhf(zg);
            cf[j] = cn;
            hf[j] = fo * tanhf(cn);
        }
        *(float4*)(g_genc + idx)   = c4;
        *(float4*)(genh_out + idx) = h4;
    }
}

// ==========================================================================
// Class cell (single-buffer staging, R14-proven): 36 in-ch = 3 chunks of 12
// (frame, fresh gen_h, class_h[cid]). Writes h_new into slab wslab[t];
// accumulates out.
// ==========================================================================
#define B_SW   (9*36*48)            // 15552 floats
#define B_SIN  (12*660)
#define B_SMEM_BYTES ((B_SW + B_SIN + 48)*4)

__device__ __forceinline__ float4 ldsrc_cls(const float* __restrict__ frame,
                                            const float* __restrict__ genh_new,
                                            const float* __restrict__ chh,
                                            int ch, int pidx, int q, bool ok)
{
    if (!ok) return make_float4(0.f, 0.f, 0.f, 0.f);
    const float* src = (ch == 0) ? frame + (size_t)(pidx & 4095)*12
                     : (ch == 1) ? genh_new + (size_t)pidx*12
                                 : chh + (size_t)pidx*12;
    return *(const float4*)(src + q*4);
}

__global__ __launch_bounds__(768, 1)
void cls_cell_kernel(const float* __restrict__ x, const int* __restrict__ class_ids,
                     const float* __restrict__ bias, int t, int par,
                     float* __restrict__ out)
{
    extern __shared__ float smem[];
    float* sW  = smem;
    float* sIn = smem + B_SW;
    float* sB  = smem + B_SW + B_SIN;

    const int tid = threadIdx.x;
    const int tx  = tid & 63;
    const int rg  = (tid >> 6) & 3;
    const int th  = tid >> 8;
    const int b   = blockIdx.y;
    const int y0  = blockIdx.x * 8;
    const int cid = __ldg(class_ids + t);

    const float* genh_new = g_genh[par ^ 1];
    const float* chh      = g_slabs[g_rslab[t*4 + cid]];
    float*       hnew     = g_slabs[g_wslab[t]];
    const float* frame    = x + (size_t)(b*NTT + t)*4096*12;

    {
        const float4* s4 = (const float4*)g_wc;
        float4*       d4 = (float4*)sW;
        #pragma unroll
        for (int i = 0; i < 6; ++i) {
            int e = tid + i*768;
            if (e < 3888) d4[e] = s4[e];
        }
    }
    if (tid < 12) ((float4*)sB)[tid] = ((const float4*)bias)[tid];

    int ppx[3], pq[3], ppidx[3];
    bool pok[3], pinr[3];
    #pragma unroll
    for (int i = 0; i < 3; ++i) {
        int e  = tid + i*768;
        bool inr = e < 1980;
        int px = e/3, q = e - px*3;
        int yy = px/66, xx = px - yy*66;
        int gy = y0 + yy - 1, gx = xx - 1;
        bool inb = inr && (unsigned)gy < 64u && (unsigned)gx < 64u;
        ppx[i] = px; pq[i] = q;
        ppidx[i] = inb ? ((b*64 + gy)*64 + gx) : 0;
        pok[i] = inb; pinr[i] = inr;
    }

    ull acc0[8], acc1[8];
    #pragma unroll
    for (int p = 0; p < 8; ++p) { acc0[p] = 0ull; acc1[p] = 0ull; }

    float4 pf[3];
    #pragma unroll
    for (int i = 0; i < 3; ++i)
        pf[i] = ldsrc_cls(frame, genh_new, chh, 0, ppidx[i], pq[i], pok[i]);

    #pragma unroll 1
    for (int ch = 0; ch < 3; ++ch) {
        __syncthreads();
        #pragma unroll
        for (int i = 0; i < 3; ++i) {
            if (pinr[i]) {
                int base = pq[i]*4*660 + ppx[i];
                sIn[base]        = pf[i].x;
                sIn[base +  660] = pf[i].y;
                sIn[base + 1320] = pf[i].z;
                sIn[base + 1980] = pf[i].w;
            }
        }
        __syncthreads();
        if (ch < 2) {
            #pragma unroll
            for (int i = 0; i < 3; ++i)
                pf[i] = ldsrc_cls(frame, genh_new, chh, ch + 1, ppidx[i], pq[i], pok[i]);
        }

        #pragma unroll 1
        for (int k = 0; k < 9; ++k) {
            const int ky = k / 3;
            const int kx = k - ky*3;
            conv12t(sW + ((k*36 + ch*12)*3 + th)*16,
                    sIn + (rg*2 + ky)*66 + tx + kx,
                    acc0, acc1);
        }
    }

    float* chc = g_class_c + (size_t)cid * SSLICE;

    #pragma unroll
    for (int r = 0; r < 2; ++r) {
        ull* accr = r ? acc1 : acc0;
        float z[16];
        #pragma unroll
        for (int p = 0; p < 8; ++p) {
            float2 v = unpack2(accr[p]);
            z[2*p] = v.x; z[2*p+1] = v.y;
        }
        const int gy  = y0 + rg*2 + r;
        const int idx = ((b*64 + gy)*64 + tx)*12 + th*4;
        float4 c4 = *(const float4*)(chc + idx);
        float4 o4 = *(const float4*)(out + idx);
        float4 h4;
        float* cf = (float*)&c4;
        float* hf = (float*)&h4;
        float* of = (float*)&o4;
        #pragma unroll
        for (int j = 0; j < 4; ++j) {
            float zi = z[j]      + sB[th*4 + j];
            float zf = z[4 + j]  + sB[12 + th*4 + j];
            float zg = z[8 + j]  + sB[24 + th*4 + j];
            float zo = z[12 + j] + sB[36 + th*4 + j];
            float fi = hsig(zi), ff = hsig(zf), fo = hsig(zo);
            float cn = ff * cf[j] + fi * tanhf(zg);
            float hn = fo * tanhf(cn);
            cf[j] = cn;
            hf[j] = hn;
            of[j] += hn;
        }
        *(float4*)(chc + idx)  = c4;
        *(float4*)(hnew + idx) = h4;
        *(float4*)(out + idx)  = o4;
    }
}

// --------------------------------------------------------------------------
extern "C" void kernel_launch(void* const* d_in, const int* in_sizes, int n_in,
                              void* d_out, int out_size)
{
    const float* x    = (const float*)d_in[0];
    const int*   cids = (const int*)d_in[1];
    const float* Wxg  = (const float*)d_in[2];
    const float* Whg  = (const float*)d_in[3];
    const float* bg   = (const float*)d_in[4];
    const float* Wxc  = (const float*)d_in[5];
    const float* Whc  = (const float*)d_in[6];
    const float* bc   = (const float*)d_in[7];
    float* out = (float*)d_out;

    cudaFuncSetAttribute(delta_kernel,    cudaFuncAttributeMaxDynamicSharedMemorySize, D_SMEM_BYTES);
    cudaFuncSetAttribute(gen_cell_kernel, cudaFuncAttributeMaxDynamicSharedMemorySize, G_SMEM_BYTES);
    cudaFuncSetAttribute(cls_cell_kernel, cudaFuncAttributeMaxDynamicSharedMemorySize, B_SMEM_BYTES);

    zero_kernel<<<1024, 256>>>(out, cids);
    reorder_kernel<<<64, 256>>>(Wxg, Whg, Wxc, Whc);

    for (int t = 0; t < NTT; ++t) {
        const int par = t & 1;
        if (t > 0)
            delta_kernel<<<dim3(8, 16), 768, D_SMEM_BYTES>>>(cids, t - 1);
        gen_cell_kernel<<<dim3(8, 16), 768, G_SMEM_BYTES>>>(bg, t, par);
        cls_cell_kernel<<<dim3(8, 16), 768, B_SMEM_BYTES>>>(x, cids, bc, t, par, out);
    }
}